// round 14
// baseline (speedup 1.0000x reference)
#include <cuda_runtime.h>
#include <cuda_fp16.h>
#include <cstdint>

// Problem constants
#define BB 128
#define TT 256
#define II 256
#define HH 256
#define LL 4
#define SS 3
#define KK 256
#define MTOT (BB*TT)
#define SLM ((size_t)SS * LL * MTOT)
#define NTILES (SS * (MTOT/128) * (HH/32))   // 6144

// Scratch
__device__ __half g_hh[(size_t)SS * LL * MTOT * HH];  // fp16 h (GEMM A / proj / gather)
__device__ __half g_xh[(size_t)MTOT * II];            // fp16 x
__device__ __half g_w0h[(size_t)SS * 768 * 256];      // fp16 w_ih0
__device__ __half g_wh [(size_t)SS * 3 * 768 * 256];  // fp16 w_ih
__device__ float g_ep[SLM * 8];                       // projections [sl*M + m][8] (7 used)
__device__ float g_tabctx[255 * 3 * 3];
__device__ float g_xproj[256 * 3];
__device__ int   g_cur[256];

__device__ __forceinline__ float sigf(float x) {
    return __fdividef(1.f, 1.f + __expf(-x));
}
__device__ __forceinline__ float gruf(float gr, float gz, float gn, float bh) {
    const float r = sigf(gr);
    const float z = sigf(gz);
    const float n = 2.f * sigf(2.f * (gn + r * bh)) - 1.f;
    return (1.f - z) * n;
}
__device__ __forceinline__ uint32_t smem_u32(const void* p) {
    uint32_t a;
    asm("{ .reg .u64 t; cvta.to.shared.u64 t, %1; cvt.u32.u64 %0, t; }" : "=r"(a) : "l"(p));
    return a;
}
__device__ __forceinline__ void mma_f16(float* c, const uint32_t* a, const uint32_t* b) {
    asm volatile(
        "mma.sync.aligned.m16n8k16.row.col.f32.f16.f16.f32 "
        "{%0,%1,%2,%3}, {%4,%5,%6,%7}, {%8,%9}, {%0,%1,%2,%3};"
        : "+f"(c[0]), "+f"(c[1]), "+f"(c[2]), "+f"(c[3])
        : "r"(a[0]), "r"(a[1]), "r"(a[2]), "r"(a[3]), "r"(b[0]), "r"(b[1]));
}
#define LDSM4(r0, r1, r2, r3, addr) \
    asm volatile("ldmatrix.sync.aligned.m8n8.x4.shared.b16 {%0,%1,%2,%3}, [%4];" \
        : "=r"(r0), "=r"(r1), "=r"(r2), "=r"(r3) : "r"(addr))
#define LDSM2(r0, r1, addr) \
    asm volatile("ldmatrix.sync.aligned.m8n8.x2.shared.b16 {%0,%1}, [%2];" \
        : "=r"(r0), "=r"(r1) : "r"(addr))
#define CP16(dst, src) \
    asm volatile("cp.async.cg.shared.global [%0], [%1], 16;" :: "r"(dst), "l"(src))
#define CP_COMMIT() asm volatile("cp.async.commit_group;" ::: "memory")
#define CP_WAITN(n) asm volatile("cp.async.wait_group %0;" :: "n"(n) : "memory")

// ---- GEMM SMEM: 4 rotating stages + double-buffered bias ----
#define STAGE_BYTES 28672
#define W_OFF       16384
#define SM_BIAS     114688              // 2 x 128 floats
#define SM_TOTAL    115712

// ---------------------------------------------------------------------------
// Persistent fp16 mma.sync GEMM + register-resident GRU gating.
// grid = 2 x SM count. Each CTA loops over tiles with a continuous 4-buffer
// chunk pipeline crossing tile boundaries (fill/drain paid once per CTA).
// Tile t: hb=(t&7)*32, mB=((t>>3)&255)*128, s=t>>11.
// W rows gate-interleaved per 8-col tile (tile tt -> gate tt%3, h-octet tt/3).
// ---------------------------------------------------------------------------
__global__ void __launch_bounds__(256, 2)
gru_mma_kernel(const __half* __restrict__ Ag, long long sAs,
               const __half* __restrict__ Wg, long long sWs,
               const float* __restrict__ BIg, const float* __restrict__ BHg, int sBs,
               __half* __restrict__ Ohg)
{
    extern __shared__ char smem[];
    const uint32_t sbase = smem_u32(smem);
    float* sbias = (float*)(smem + SM_BIAS);   // [2][128]

    const int tid = threadIdx.x;
    const int wid = tid >> 5;
    const int lane = tid & 31;
    const int lq = lane >> 2;
    const int lr = lane & 3;

    const int wm = (wid & 3) * 32;
    const int wn = (wid >> 2) * 48;
    const int warp_n = wid >> 2;

    const int G = gridDim.x;
    const int myNT = NTILES / G + (blockIdx.x < (NTILES % G) ? 1 : 0);
    const int myK = myNT * 4;

    const int arow = tid >> 3;
    const int seg  = tid & 7;

    // chunk c (0..myK-1): tile = blockIdx.x + (c>>2)*G, k0 = (c&3)*64
    auto load_chunk = [&](int buf, int c) {
        const int t = blockIdx.x + (c >> 2) * G;
        const int k0 = (c & 3) << 6;
        const int s  = t >> 11;
        const int mB = ((t >> 3) & 255) << 7;
        const int hb = (t & 7) << 5;
        const __half* A = Ag + (size_t)s * sAs;
        const __half* W = Wg + (size_t)s * sWs;
        const uint32_t stA = sbase + buf * STAGE_BYTES;
#pragma unroll
        for (int j = 0; j < 4; ++j) {
            const int row = arow + 32 * j;
            const uint32_t dst = stA + row * 128 + ((seg ^ (row & 7)) * 16);
            CP16(dst, A + (size_t)(mB + row) * KK + k0 + seg * 8);
        }
#pragma unroll
        for (int j = 0; j < 3; ++j) {
            const int n = arow + 32 * j;               // 0..95
            const int tt = n >> 3, cc = n & 7;
            const int grow = (tt % 3) * 256 + hb + (tt / 3) * 8 + cc;
            const uint32_t dst = stA + W_OFF + n * 128 + ((seg ^ (n & 7)) * 16);
            CP16(dst, W + (size_t)grow * KK + k0 + seg * 8);
        }
    };

    float acc[2][6][4];
#pragma unroll
    for (int mt = 0; mt < 2; mt++)
#pragma unroll
        for (int nt = 0; nt < 6; nt++)
#pragma unroll
            for (int q = 0; q < 4; q++) acc[mt][nt][q] = 0.f;

    const int rA_lo = lane & 15;
    const int sA    = lane >> 4;
    const int rB_lo = ((lane >> 4) << 3) + (lane & 7);
    const int sB    = (lane >> 3) & 1;

    auto compute = [&](int buf) {
        const uint32_t stA = sbase + buf * STAGE_BYTES;
        const uint32_t stW = stA + W_OFF;
#pragma unroll
        for (int kk = 0; kk < 4; ++kk) {
            uint32_t a[2][4];
#pragma unroll
            for (int mt = 0; mt < 2; mt++) {
                const int row = wm + mt * 16 + rA_lo;
                const uint32_t addr = stA + row * 128
                                    + (((kk * 2 + sA) ^ (row & 7)) * 16);
                LDSM4(a[mt][0], a[mt][1], a[mt][2], a[mt][3], addr);
            }
            uint32_t b[6][2];
#pragma unroll
            for (int np = 0; np < 3; np++) {
                const int n = wn + np * 16 + rB_lo;
                const uint32_t addr = stW + n * 128
                                    + (((kk * 2 + sB) ^ (n & 7)) * 16);
                uint32_t r0, r1, r2, r3;
                LDSM4(r0, r1, r2, r3, addr);
                b[2 * np][0] = r0; b[2 * np][1] = r1;
                b[2 * np + 1][0] = r2; b[2 * np + 1][1] = r3;
            }
#pragma unroll
            for (int mt = 0; mt < 2; mt++)
#pragma unroll
                for (int nt = 0; nt < 6; nt++)
                    mma_f16(acc[mt][nt], a[mt], b[nt]);
        }
    };

    // pipeline fill: 3 chunks in flight
    load_chunk(0, 0); CP_COMMIT();
    load_chunk(1, 1); CP_COMMIT();
    load_chunk(2, 2); CP_COMMIT();

#pragma unroll 1
    for (int k = 0; k < myK; ++k) {
        if (k + 2 < myK)      { CP_WAITN(2); }
        else if (k + 1 < myK) { CP_WAITN(1); }
        else                  { CP_WAITN(0); }
        __syncthreads();

        // load bias for current tile at its first chunk
        if ((k & 3) == 0 && tid < 128) {
            const int t = blockIdx.x + (k >> 2) * G;
            const int s = t >> 11;
            const int hb = (t & 7) << 5;
            const float* BI = BIg + s * sBs;
            const float* BH = BHg + s * sBs;
            float v;
            if (tid < 32)       v = __ldg(&BI[hb + tid])            + __ldg(&BH[hb + tid]);
            else if (tid < 64)  v = __ldg(&BI[256 + hb + tid - 32]) + __ldg(&BH[256 + hb + tid - 32]);
            else if (tid < 96)  v = __ldg(&BI[512 + hb + tid - 64]);
            else                v = __ldg(&BH[512 + hb + tid - 96]);
            sbias[((k >> 2) & 1) * 128 + tid] = v;
        }

        if (k + 3 < myK) { load_chunk((k + 3) & 3, k + 3); CP_COMMIT(); }

        compute(k & 3);

        if ((k & 3) == 3) {
            // -------- register-resident GRU epilogue for tile k>>2 --------
            const int i = k >> 2;
            const int t = blockIdx.x + i * G;
            const int s = t >> 11;
            const int mB = ((t >> 3) & 255) << 7;
            const int hb = (t & 7) << 5;
            __half* Oh = Ohg + (size_t)s * ((size_t)LL * MTOT * HH);
            const float* sb = sbias + (i & 1) * 128;
#pragma unroll
            for (int o = 0; o < 2; ++o) {
                const int hl = (warp_n * 2 + o) * 8 + 2 * lr;
                const float br0 = sb[hl],       br1 = sb[hl + 1];
                const float bz0 = sb[32 + hl],  bz1 = sb[33 + hl];
                const float bn0 = sb[64 + hl],  bn1 = sb[65 + hl];
                const float bh0 = sb[96 + hl],  bh1 = sb[97 + hl];
#pragma unroll
                for (int mt = 0; mt < 2; ++mt) {
#pragma unroll
                    for (int hf = 0; hf < 2; ++hf) {
                        const int row = mB + wm + mt * 16 + lq + hf * 8;
                        const int q = hf * 2;
                        const float hv0 = gruf(acc[mt][o * 3 + 0][q]     + br0,
                                               acc[mt][o * 3 + 1][q]     + bz0,
                                               acc[mt][o * 3 + 2][q]     + bn0, bh0);
                        const float hv1 = gruf(acc[mt][o * 3 + 0][q + 1] + br1,
                                               acc[mt][o * 3 + 1][q + 1] + bz1,
                                               acc[mt][o * 3 + 2][q + 1] + bn1, bh1);
                        *(__half2*)&Oh[(size_t)row * HH + hb + hl] =
                            __floats2half2_rn(hv0, hv1);
                    }
                }
            }
            // reset accumulators for next tile
#pragma unroll
            for (int mt = 0; mt < 2; mt++)
#pragma unroll
                for (int nt = 0; nt < 6; nt++)
#pragma unroll
                    for (int q = 0; q < 4; q++) acc[mt][nt][q] = 0.f;
        }
    }
}

// ---------------------------------------------------------------------------
// Skinny projection GEMM (per-layer): g_ep rows of plane (s, layer).
// ---------------------------------------------------------------------------
#define PJ_STAGE 16384
#define PJ_B_OFF 49152
#define PJ_TOTAL 53376
#define PJ_BSTRIDE 264

__global__ void __launch_bounds__(256)
proj_kernel(const float* __restrict__ w_lw, const float* __restrict__ w_sel,
            int layer)
{
    extern __shared__ char smem[];
    const uint32_t sbase = smem_u32(smem);
    __half* Bs = (__half*)(smem + PJ_B_OFF);

    const int tid = threadIdx.x;
    const int wid = tid >> 5;
    const int lane = tid & 31;
    const int lq = lane >> 2;
    const int lr = lane & 3;

    const int s = blockIdx.y;
    const size_t rowBase = ((size_t)(s * LL + layer) * MTOT) + (size_t)blockIdx.x * 128;
    const __half* A = g_hh + rowBase * 256;

    for (int i = tid; i < 8 * PJ_BSTRIDE; i += 256) {
        const int n = i / PJ_BSTRIDE, k = i % PJ_BSTRIDE;
        float v = 0.f;
        if (k < 256 && n < 7)
            v = (n < 4) ? __ldg(&w_lw[n * 256 + k]) : __ldg(&w_sel[(n - 4) * 512 + k]);
        Bs[i] = __float2half_rn(v);
    }

    const int arow = tid >> 3;
    const int seg  = tid & 7;
    auto load_stage = [&](int buf, int k0) {
        const uint32_t st = sbase + buf * PJ_STAGE;
#pragma unroll
        for (int j = 0; j < 4; ++j) {
            const int row = arow + 32 * j;
            const uint32_t dst = st + row * 128 + ((seg ^ (row & 7)) * 16);
            CP16(dst, A + (size_t)row * 256 + k0 + seg * 8);
        }
    };

    const int rA_lo = lane & 15;
    const int sA    = lane >> 4;
    const int l4    = lane & 15;
    const uint32_t bAddrBase = sbase + PJ_B_OFF
                             + (uint32_t)((l4 & 7) * PJ_BSTRIDE * 2 + ((l4 >> 3) & 1) * 16);

    float acc[4] = {0.f, 0.f, 0.f, 0.f};

    load_stage(0, 0);   CP_COMMIT();
    load_stage(1, 64);  CP_COMMIT();

#pragma unroll 1
    for (int st = 0; st < 4; ++st) {
        CP_WAITN(1);
        __syncthreads();
        const uint32_t stA = sbase + (st % 3) * PJ_STAGE;

#pragma unroll
        for (int kk = 0; kk < 4; ++kk) {
            uint32_t a[4];
            const int row = wid * 16 + rA_lo;
            const uint32_t addr = stA + row * 128
                                + (((kk * 2 + sA) ^ (row & 7)) * 16);
            LDSM4(a[0], a[1], a[2], a[3], addr);

            uint32_t b[2];
            const int k0 = st * 64 + kk * 16;
            LDSM2(b[0], b[1], bAddrBase + k0 * 2);

            mma_f16(acc, a, b);
        }

        if (st + 2 < 4) load_stage((st + 2) % 3, (st + 2) * 64);
        CP_COMMIT();
    }

    const size_t r0 = rowBase + wid * 16 + lq;
    *(float2*)(g_ep + r0 * 8 + 2 * lr)       = make_float2(acc[0], acc[1]);
    *(float2*)(g_ep + (r0 + 8) * 8 + 2 * lr) = make_float2(acc[2], acc[3]);
}

// ---------------------------------------------------------------------------
__global__ __launch_bounds__(256)
void f2h_kernel(const float* __restrict__ src, __half* __restrict__ dst, int n4)
{
    const int i = blockIdx.x * 256 + threadIdx.x;
    if (i < n4) {
        const float4 v = __ldg((const float4*)src + i);
        __half2* d = (__half2*)dst + 2 * i;
        d[0] = __floats2half2_rn(v.x, v.y);
        d[1] = __floats2half2_rn(v.z, v.w);
    }
}

// ---------------------------------------------------------------------------
__global__ __launch_bounds__(256)
void table_kernel(const float* __restrict__ hidden,
                  const float* __restrict__ b_lw)
{
    const int t = blockIdx.x;
    const int s = blockIdx.y;
    const int tid = threadIdx.x;
    const int lane = tid & 31;
    const int wp = tid >> 5;

    __shared__ float ep[512][8];
    __shared__ float red[4][3];

    for (int i = tid; i < 1024; i += 256) {
        const int p = i >> 1;
        const int half = i & 1;
        const int b = p >> 2, l = p & 3;
        const size_t idx = (((size_t)(s * LL + l) * MTOT + (size_t)b * TT + t) * 8
                           + half * 4);
        ((float4*)ep)[i] = *(const float4*)(g_ep + idx);
    }
    __syncthreads();

    float sc[3] = {0.f, 0.f, 0.f};
    if (tid < 128) {
        const int b = tid;
        float bl[4];
#pragma unroll
        for (int lp = 0; lp < 4; lp++) bl[lp] = __ldg(&b_lw[lp]);
        float attn[4];
#pragma unroll
        for (int l = 0; l < 4; l++) {
            float a = 0.f;
#pragma unroll
            for (int lp = 0; lp < 4; lp++)
                a += __ldg(&hidden[b * 16 + l * 4 + lp]) * (ep[b * 4 + l][lp] + bl[lp]);
            attn[l] = a;
        }
        const float mx = fmaxf(fmaxf(attn[0], attn[1]), fmaxf(attn[2], attn[3]));
        float ee[4], ssum = 0.f;
#pragma unroll
        for (int l = 0; l < 4; l++) { ee[l] = __expf(attn[l] - mx); ssum += ee[l]; }
        const float inv = 1.f / ssum;
#pragma unroll
        for (int l = 0; l < 4; l++) {
            const float a = ee[l] * inv;
#pragma unroll
            for (int q = 0; q < 3; q++) sc[q] += a * ep[b * 4 + l][4 + q];
        }
#pragma unroll
        for (int q = 0; q < 3; q++)
#pragma unroll
            for (int off = 16; off; off >>= 1)
                sc[q] += __shfl_xor_sync(0xffffffffu, sc[q], off);
        if (lane == 0) { red[wp][0] = sc[0]; red[wp][1] = sc[1]; red[wp][2] = sc[2]; }
    }
    __syncthreads();
    if (tid < 3) {
        const float v = red[0][tid] + red[1][tid] + red[2][tid] + red[3][tid];
        g_tabctx[(t * 3 + s) * 3 + tid] = v;
    }
}

__global__ __launch_bounds__(256)
void xproj_kernel(const float* __restrict__ x,
                  const float* __restrict__ w_sel,
                  const float* __restrict__ b_sel)
{
    const int tau = blockIdx.x + 1;
    const int tid = threadIdx.x;
    const int lane = tid & 31, wp = tid >> 5;
    __shared__ float red[3][8];
    float xs = 0.f;
    const float* xp = x + (size_t)tau * II + tid;
#pragma unroll 4
    for (int b = 0; b < 128; b++) xs += __ldg(&xp[(size_t)b * TT * II]);
    float sc[3];
#pragma unroll
    for (int q = 0; q < 3; q++) sc[q] = xs * __ldg(&w_sel[q * 512 + 256 + tid]);
#pragma unroll
    for (int q = 0; q < 3; q++)
#pragma unroll
        for (int off = 16; off; off >>= 1)
            sc[q] += __shfl_xor_sync(0xffffffffu, sc[q], off);
    if (lane == 0) { red[0][wp] = sc[0]; red[1][wp] = sc[1]; red[2][wp] = sc[2]; }
    __syncthreads();
    if (tid < 3) {
        float v = 0.f;
#pragma unroll
        for (int w2 = 0; w2 < 8; w2++) v += red[tid][w2];
        g_xproj[tau * 3 + tid] = v + 128.f * __ldg(&b_sel[tid]);
    }
}

__global__ void serial_kernel()
{
    __shared__ float tab[255 * 9];
    __shared__ float xp[256 * 3];
    const int tid = threadIdx.x;
    for (int i = tid; i < 255 * 9; i += 256) tab[i] = g_tabctx[i];
    for (int i = tid; i < 256 * 3; i += 256) xp[i] = g_xproj[i];
    __syncthreads();
    if (tid == 0) {
        g_cur[0] = 0;
        int cur = 0;
        for (int tau = 1; tau < 256; tau++) {
            const float* tv = &tab[((tau - 1) * 3 + cur) * 3];
            const float v0 = tv[0] + xp[tau * 3 + 0];
            const float v1 = tv[1] + xp[tau * 3 + 1];
            const float v2 = tv[2] + xp[tau * 3 + 2];
            int c = 0; float best = v0;
            if (v1 > best) { best = v1; c = 1; }
            if (v2 > best) { best = v2; c = 2; }
            cur = c; g_cur[tau] = c;
        }
    }
}

__global__ __launch_bounds__(256)
void gather_kernel(float* __restrict__ out, long long n)
{
    const long long idx = (long long)blockIdx.x * 256 + threadIdx.x;
    if (idx >= n) return;
    const long long BTH = (long long)BB * TT * HH;
    int b, t, h;
    if (idx < BTH) {
        b = (int)(idx >> 16);
        const int r = (int)(idx & 65535);
        t = r >> 8; h = r & 255;
    } else {
        const long long j = idx - BTH;
        if (j >= (long long)BB * HH) { out[idx] = 0.f; return; }
        b = (int)(j >> 8); h = (int)(j & 255); t = TT - 1;
    }
    const int cur = g_cur[t];
    out[idx] = __half2float(
        g_hh[((size_t)(cur * LL + (LL - 1)) * MTOT + (size_t)b * TT + t) * HH + h]);
}

// ---------------------------------------------------------------------------
extern "C" void kernel_launch(void* const* d_in, const int* in_sizes, int n_in,
                              void* d_out, int out_size)
{
    (void)in_sizes; (void)n_in;
    const float* x      = (const float*)d_in[0];
    const float* hidden = (const float*)d_in[1];
    const float* w_ih0  = (const float*)d_in[2];
    const float* b_ih0  = (const float*)d_in[3];
    const float* b_hh0  = (const float*)d_in[4];
    const float* w_ih   = (const float*)d_in[5];
    const float* b_ih   = (const float*)d_in[6];
    const float* b_hh   = (const float*)d_in[7];
    const float* w_lw   = (const float*)d_in[8];
    const float* b_lw   = (const float*)d_in[9];
    const float* w_sel  = (const float*)d_in[10];
    const float* b_sel  = (const float*)d_in[11];
    float* out = (float*)d_out;

    __half *xh, *w0h, *wh, *hh;
    cudaGetSymbolAddress((void**)&xh,  g_xh);
    cudaGetSymbolAddress((void**)&w0h, g_w0h);
    cudaGetSymbolAddress((void**)&wh,  g_wh);
    cudaGetSymbolAddress((void**)&hh,  g_hh);

    int sms = 148;
    cudaDeviceGetAttribute(&sms, cudaDevAttrMultiProcessorCount, 0);
    const int G = 2 * sms;

    f2h_kernel<<<(MTOT * II / 4 + 255) / 256, 256>>>(x, xh, MTOT * II / 4);
    f2h_kernel<<<(SS * 768 * 256 / 4 + 255) / 256, 256>>>(w_ih0, w0h, SS * 768 * 256 / 4);
    f2h_kernel<<<(SS * 3 * 768 * 256 / 4 + 255) / 256, 256>>>(w_ih, wh, SS * 3 * 768 * 256 / 4);

    cudaFuncSetAttribute(gru_mma_kernel,
                         cudaFuncAttributeMaxDynamicSharedMemorySize, SM_TOTAL);
    cudaFuncSetAttribute(proj_kernel,
                         cudaFuncAttributeMaxDynamicSharedMemorySize, PJ_TOTAL);

    const dim3 gProj(MTOT / 128, SS);
    const size_t hstride = (size_t)LL * MTOT * HH;

    // layer 0, then L2-hot projection for layer 0
    gru_mma_kernel<<<G, 256, SM_TOTAL>>>(
        xh, 0, w0h, (long long)768 * 256,
        b_ih0, b_hh0, 768,
        hh + 0 * (size_t)MTOT * HH);
    proj_kernel<<<gProj, 256, PJ_TOTAL>>>(w_lw, w_sel, 0);

    for (int l = 1; l < LL; l++) {
        gru_mma_kernel<<<G, 256, SM_TOTAL>>>(
            hh + (size_t)(l - 1) * MTOT * HH, (long long)hstride,
            wh + (size_t)(l - 1) * 768 * 256, (long long)3 * 768 * 256,
            b_ih + (size_t)(l - 1) * 768,
            b_hh + (size_t)(l - 1) * 768, 3 * 768,
            hh + (size_t)l * MTOT * HH);
        proj_kernel<<<gProj, 256, PJ_TOTAL>>>(w_lw, w_sel, l);
    }

    xproj_kernel<<<255, 256>>>(x, w_sel, b_sel);
    table_kernel<<<dim3(255, 3), 256>>>(hidden, b_lw);
    serial_kernel<<<1, 256>>>();

    const long long n = (long long)out_size;
    const int nb = (int)((n + 255) / 256);
    gather_kernel<<<nb, 256>>>(out, n);
}

// round 15
// speedup vs baseline: 1.0446x; 1.0446x over previous
#include <cuda_runtime.h>
#include <cuda_fp16.h>
#include <cstdint>

// Problem constants
#define BB 128
#define TT 256
#define II 256
#define HH 256
#define LL 4
#define SS 3
#define KK 256
#define MTOT (BB*TT)
#define SLM ((size_t)SS * LL * MTOT)
#define NTILES 6144   // SS * (MTOT/128) * (HH/32)

// Scratch
__device__ __half g_hh[(size_t)SS * LL * MTOT * HH];  // fp16 h (GEMM A / proj / gather)
__device__ __half g_xh[(size_t)MTOT * II];            // fp16 x
__device__ __half g_w0h[(size_t)SS * 768 * 256];      // fp16 w_ih0
__device__ __half g_wh [(size_t)SS * 3 * 768 * 256];  // fp16 w_ih
__device__ float g_ep[SLM * 8];                       // projections [sl*M + m][8]
__device__ float g_tabctx[255 * 3 * 3];
__device__ float g_xproj[256 * 3];
__device__ int   g_cur[256];

__device__ __forceinline__ float sigf(float x) {
    return __fdividef(1.f, 1.f + __expf(-x));
}
__device__ __forceinline__ float gruf(float gr, float gz, float gn, float bh) {
    const float r = sigf(gr);
    const float z = sigf(gz);
    const float n = 2.f * sigf(2.f * (gn + r * bh)) - 1.f;
    return (1.f - z) * n;
}
__device__ __forceinline__ uint32_t smem_u32(const void* p) {
    uint32_t a;
    asm("{ .reg .u64 t; cvta.to.shared.u64 t, %1; cvt.u32.u64 %0, t; }" : "=r"(a) : "l"(p));
    return a;
}
__device__ __forceinline__ void mma_f16(float* c, const uint32_t* a, const uint32_t* b) {
    asm volatile(
        "mma.sync.aligned.m16n8k16.row.col.f32.f16.f16.f32 "
        "{%0,%1,%2,%3}, {%4,%5,%6,%7}, {%8,%9}, {%0,%1,%2,%3};"
        : "+f"(c[0]), "+f"(c[1]), "+f"(c[2]), "+f"(c[3])
        : "r"(a[0]), "r"(a[1]), "r"(a[2]), "r"(a[3]), "r"(b[0]), "r"(b[1]));
}
#define LDSM4(r0, r1, r2, r3, addr) \
    asm volatile("ldmatrix.sync.aligned.m8n8.x4.shared.b16 {%0,%1,%2,%3}, [%4];" \
        : "=r"(r0), "=r"(r1), "=r"(r2), "=r"(r3) : "r"(addr))
#define LDSM2(r0, r1, addr) \
    asm volatile("ldmatrix.sync.aligned.m8n8.x2.shared.b16 {%0,%1}, [%2];" \
        : "=r"(r0), "=r"(r1) : "r"(addr))
#define CP16(dst, src) \
    asm volatile("cp.async.cg.shared.global [%0], [%1], 16;" :: "r"(dst), "l"(src))
#define CP_COMMIT() asm volatile("cp.async.commit_group;" ::: "memory")
#define CP_WAITN(n) asm volatile("cp.async.wait_group %0;" :: "n"(n) : "memory")

// ---- GEMM SMEM: 4 stages x (A[128][64]h + W[96][64]h); bias @ 114688 ----
#define STAGE_BYTES 28672
#define W_OFF       16384
#define SM_BIAS     114688
#define SM_TOTAL    115200

// ---- proj SMEM layout (within the same dynamic smem) ----
#define PJ_STAGE 16384
#define PJ_B_OFF 49152
#define PJ_BSTRIDE 264

// ---------------------------------------------------------------------------
// proj body: one 128-row block of g_ep[plane(s,layer)] = hh * P^T
// ---------------------------------------------------------------------------
__device__ void proj_body(char* smem, int e, int layer,
                          const float* __restrict__ w_lw,
                          const float* __restrict__ w_sel)
{
    const uint32_t sbase = smem_u32(smem);
    __half* Bs = (__half*)(smem + PJ_B_OFF);

    const int tid = threadIdx.x;
    const int wid = tid >> 5;
    const int lane = tid & 31;
    const int lq = lane >> 2;
    const int lr = lane & 3;

    const int s = e >> 8;              // 0..2
    const int mblk = e & 255;
    const size_t rowBase = ((size_t)(s * LL + layer) * MTOT) + (size_t)mblk * 128;
    const __half* A = g_hh + rowBase * 256;

    for (int i = tid; i < 8 * PJ_BSTRIDE; i += 256) {
        const int n = i / PJ_BSTRIDE, k = i % PJ_BSTRIDE;
        float v = 0.f;
        if (k < 256 && n < 7)
            v = (n < 4) ? __ldg(&w_lw[n * 256 + k]) : __ldg(&w_sel[(n - 4) * 512 + k]);
        Bs[i] = __float2half_rn(v);
    }

    const int arow = tid >> 3;
    const int seg  = tid & 7;
    auto load_stage = [&](int buf, int k0) {
        const uint32_t st = sbase + buf * PJ_STAGE;
#pragma unroll
        for (int j = 0; j < 4; ++j) {
            const int row = arow + 32 * j;
            const uint32_t dst = st + row * 128 + ((seg ^ (row & 7)) * 16);
            CP16(dst, A + (size_t)row * 256 + k0 + seg * 8);
        }
    };

    const int rA_lo = lane & 15;
    const int sA    = lane >> 4;
    const int l4    = lane & 15;
    const uint32_t bAddrBase = sbase + PJ_B_OFF
                             + (uint32_t)((l4 & 7) * PJ_BSTRIDE * 2 + ((l4 >> 3) & 1) * 16);

    float acc[4] = {0.f, 0.f, 0.f, 0.f};

    load_stage(0, 0);   CP_COMMIT();
    load_stage(1, 64);  CP_COMMIT();

#pragma unroll 1
    for (int st = 0; st < 4; ++st) {
        CP_WAITN(1);
        __syncthreads();
        const uint32_t stA = sbase + (st % 3) * PJ_STAGE;

#pragma unroll
        for (int kk = 0; kk < 4; ++kk) {
            uint32_t a[4];
            const int row = wid * 16 + rA_lo;
            const uint32_t addr = stA + row * 128
                                + (((kk * 2 + sA) ^ (row & 7)) * 16);
            LDSM4(a[0], a[1], a[2], a[3], addr);

            uint32_t b[2];
            const int k0 = st * 64 + kk * 16;
            LDSM2(b[0], b[1], bAddrBase + k0 * 2);

            mma_f16(acc, a, b);
        }

        if (st + 2 < 4) load_stage((st + 2) % 3, (st + 2) * 64);
        CP_COMMIT();
    }

    const size_t r0 = rowBase + wid * 16 + lq;
    *(float2*)(g_ep + r0 * 8 + 2 * lr)       = make_float2(acc[0], acc[1]);
    *(float2*)(g_ep + (r0 + 8) * 8 + 2 * lr) = make_float2(acc[2], acc[3]);
}

// ---------------------------------------------------------------------------
// xproj body: one tau (= e + 1)
// ---------------------------------------------------------------------------
__device__ void xproj_body(int e,
                           const float* __restrict__ x,
                           const float* __restrict__ w_sel,
                           const float* __restrict__ b_sel)
{
    __shared__ float red[3][8];
    const int tau = e + 1;
    const int tid = threadIdx.x;
    const int lane = tid & 31, wp = tid >> 5;
    float xs = 0.f;
    const float* xp = x + (size_t)tau * II + tid;
#pragma unroll 4
    for (int b = 0; b < 128; b++) xs += __ldg(&xp[(size_t)b * TT * II]);
    float sc[3];
#pragma unroll
    for (int q = 0; q < 3; q++) sc[q] = xs * __ldg(&w_sel[q * 512 + 256 + tid]);
#pragma unroll
    for (int q = 0; q < 3; q++)
#pragma unroll
        for (int off = 16; off; off >>= 1)
            sc[q] += __shfl_xor_sync(0xffffffffu, sc[q], off);
    if (lane == 0) { red[0][wp] = sc[0]; red[1][wp] = sc[1]; red[2][wp] = sc[2]; }
    __syncthreads();
    if (tid < 3) {
        float v = 0.f;
#pragma unroll
        for (int w2 = 0; w2 < 8; w2++) v += red[tid][w2];
        g_xproj[tau * 3 + tid] = v + 128.f * __ldg(&b_sel[tid]);
    }
}

// ---------------------------------------------------------------------------
// Fused GEMM launch: blocks [0, NTILES) do the fp16 GEMM+GRU (R13 structure);
// blocks >= NTILES do side work (mode 1: xproj, mode 2: proj of prev layer).
// ---------------------------------------------------------------------------
__global__ void __launch_bounds__(256, 2)
gru_mma_kernel(const __half* __restrict__ Ag, long long sAs,
               const __half* __restrict__ Wg, long long sWs,
               const float* __restrict__ BIg, const float* __restrict__ BHg, int sBs,
               __half* __restrict__ Ohg,
               const float* __restrict__ w_lw, const float* __restrict__ w_sel,
               const float* __restrict__ x, const float* __restrict__ b_sel,
               int mode, int proj_layer)
{
    extern __shared__ char smem[];

    const int bid = blockIdx.x;
    if (bid >= NTILES) {
        const int e = bid - NTILES;
        if (mode == 1) xproj_body(e, x, w_sel, b_sel);
        else           proj_body(smem, e, proj_layer, w_lw, w_sel);
        return;
    }

    const uint32_t sbase = smem_u32(smem);
    float* sbias = (float*)(smem + SM_BIAS);

    const int tid = threadIdx.x;
    const int wid = tid >> 5;
    const int lane = tid & 31;
    const int lq = lane >> 2;
    const int lr = lane & 3;

    // decode: hb fastest (A-tile locality), then mB, then s
    const int hb = (bid & 7) << 5;
    const int mBase = ((bid >> 3) & 255) << 7;
    const int s = bid >> 11;

    const __half* A = Ag + (size_t)s * sAs;
    const __half* W = Wg + (size_t)s * sWs;
    const float* BI = BIg + s * sBs;
    const float* BH = BHg + s * sBs;
    __half* Oh = Ohg + (size_t)s * ((size_t)LL * MTOT * HH);

    const int wm = (wid & 3) * 32;
    const int wn = (wid >> 2) * 48;
    const int warp_n = wid >> 2;

    const int arow = tid >> 3;
    const int seg  = tid & 7;
    auto load_stage = [&](int buf, int k0) {
        const uint32_t stA = sbase + buf * STAGE_BYTES;
#pragma unroll
        for (int j = 0; j < 4; ++j) {
            const int row = arow + 32 * j;
            const uint32_t dst = stA + row * 128 + ((seg ^ (row & 7)) * 16);
            CP16(dst, A + (size_t)(mBase + row) * KK + k0 + seg * 8);
        }
#pragma unroll
        for (int j = 0; j < 3; ++j) {
            const int n = arow + 32 * j;               // 0..95
            const int t = n >> 3, c = n & 7;
            const int grow = (t % 3) * 256 + hb + (t / 3) * 8 + c;  // gate-interleaved
            const uint32_t dst = stA + W_OFF + n * 128 + ((seg ^ (n & 7)) * 16);
            CP16(dst, W + (size_t)grow * KK + k0 + seg * 8);
        }
    };

    // prefetch entire K (4 chunks of 64), one commit group each
    load_stage(0, 0);   CP_COMMIT();
    load_stage(1, 64);  CP_COMMIT();
    load_stage(2, 128); CP_COMMIT();
    load_stage(3, 192); CP_COMMIT();

    if (tid < 32)       sbias[tid] = __ldg(&BI[hb + tid])            + __ldg(&BH[hb + tid]);
    else if (tid < 64)  sbias[tid] = __ldg(&BI[256 + hb + tid - 32]) + __ldg(&BH[256 + hb + tid - 32]);
    else if (tid < 96)  sbias[tid] = __ldg(&BI[512 + hb + tid - 64]);
    else if (tid < 128) sbias[tid] = __ldg(&BH[512 + hb + tid - 96]);

    float acc[2][6][4];
#pragma unroll
    for (int mt = 0; mt < 2; mt++)
#pragma unroll
        for (int nt = 0; nt < 6; nt++)
#pragma unroll
            for (int q = 0; q < 4; q++) acc[mt][nt][q] = 0.f;

    const int rA_lo = lane & 15;
    const int sA    = lane >> 4;
    const int rB_lo = ((lane >> 4) << 3) + (lane & 7);
    const int sB    = (lane >> 3) & 1;

    auto compute = [&](int buf) {
        const uint32_t stA = sbase + buf * STAGE_BYTES;
        const uint32_t stW = stA + W_OFF;
#pragma unroll
        for (int kk = 0; kk < 4; ++kk) {
            uint32_t a[2][4];
#pragma unroll
            for (int mt = 0; mt < 2; mt++) {
                const int row = wm + mt * 16 + rA_lo;
                const uint32_t addr = stA + row * 128
                                    + (((kk * 2 + sA) ^ (row & 7)) * 16);
                LDSM4(a[mt][0], a[mt][1], a[mt][2], a[mt][3], addr);
            }
            uint32_t b[6][2];
#pragma unroll
            for (int np = 0; np < 3; np++) {
                const int n = wn + np * 16 + rB_lo;
                const uint32_t addr = stW + n * 128
                                    + (((kk * 2 + sB) ^ (n & 7)) * 16);
                uint32_t r0, r1, r2, r3;
                LDSM4(r0, r1, r2, r3, addr);
                b[2 * np][0] = r0; b[2 * np][1] = r1;
                b[2 * np + 1][0] = r2; b[2 * np + 1][1] = r3;
            }
#pragma unroll
            for (int mt = 0; mt < 2; mt++)
#pragma unroll
                for (int nt = 0; nt < 6; nt++)
                    mma_f16(acc[mt][nt], a[mt], b[nt]);
        }
    };

    CP_WAITN(3); __syncthreads(); compute(0);
    CP_WAITN(2); __syncthreads(); compute(1);
    CP_WAITN(1); __syncthreads(); compute(2);
    CP_WAITN(0); __syncthreads(); compute(3);

    // -------- register-resident GRU epilogue (fp16 store only) --------
#pragma unroll
    for (int o = 0; o < 2; ++o) {
        const int hl = (warp_n * 2 + o) * 8 + 2 * lr;
        const float br0 = sbias[hl],       br1 = sbias[hl + 1];
        const float bz0 = sbias[32 + hl],  bz1 = sbias[33 + hl];
        const float bn0 = sbias[64 + hl],  bn1 = sbias[65 + hl];
        const float bh0 = sbias[96 + hl],  bh1 = sbias[97 + hl];
#pragma unroll
        for (int mt = 0; mt < 2; ++mt) {
#pragma unroll
            for (int hf = 0; hf < 2; ++hf) {
                const int row = mBase + wm + mt * 16 + lq + hf * 8;
                const int q = hf * 2;
                const float hv0 = gruf(acc[mt][o * 3 + 0][q]     + br0,
                                       acc[mt][o * 3 + 1][q]     + bz0,
                                       acc[mt][o * 3 + 2][q]     + bn0, bh0);
                const float hv1 = gruf(acc[mt][o * 3 + 0][q + 1] + br1,
                                       acc[mt][o * 3 + 1][q + 1] + bz1,
                                       acc[mt][o * 3 + 2][q + 1] + bn1, bh1);
                *(__half2*)&Oh[(size_t)row * HH + hb + hl] = __floats2half2_rn(hv0, hv1);
            }
        }
    }
}

// ---------------------------------------------------------------------------
// Standalone proj launch (for the final layer)
// ---------------------------------------------------------------------------
__global__ void __launch_bounds__(256, 2)
proj_kernel(const float* __restrict__ w_lw, const float* __restrict__ w_sel,
            int layer)
{
    extern __shared__ char smem[];
    proj_body(smem, blockIdx.x, layer, w_lw, w_sel);
}

// ---------------------------------------------------------------------------
__global__ __launch_bounds__(256)
void f2h_kernel(const float* __restrict__ src, __half* __restrict__ dst, int n4)
{
    const int i = blockIdx.x * 256 + threadIdx.x;
    if (i < n4) {
        const float4 v = __ldg((const float4*)src + i);
        __half2* d = (__half2*)dst + 2 * i;
        d[0] = __floats2half2_rn(v.x, v.y);
        d[1] = __floats2half2_rn(v.z, v.w);
    }
}

// ---------------------------------------------------------------------------
__global__ __launch_bounds__(256)
void table_kernel(const float* __restrict__ hidden,
                  const float* __restrict__ b_lw)
{
    const int t = blockIdx.x;
    const int s = blockIdx.y;
    const int tid = threadIdx.x;
    const int lane = tid & 31;
    const int wp = tid >> 5;

    __shared__ float ep[512][8];
    __shared__ float red[4][3];

    for (int i = tid; i < 1024; i += 256) {
        const int p = i >> 1;
        const int half = i & 1;
        const int b = p >> 2, l = p & 3;
        const size_t idx = (((size_t)(s * LL + l) * MTOT + (size_t)b * TT + t) * 8
                           + half * 4);
        ((float4*)ep)[i] = *(const float4*)(g_ep + idx);
    }
    __syncthreads();

    float sc[3] = {0.f, 0.f, 0.f};
    if (tid < 128) {
        const int b = tid;
        float bl[4];
#pragma unroll
        for (int lp = 0; lp < 4; lp++) bl[lp] = __ldg(&b_lw[lp]);
        float attn[4];
#pragma unroll
        for (int l = 0; l < 4; l++) {
            float a = 0.f;
#pragma unroll
            for (int lp = 0; lp < 4; lp++)
                a += __ldg(&hidden[b * 16 + l * 4 + lp]) * (ep[b * 4 + l][lp] + bl[lp]);
            attn[l] = a;
        }
        const float mx = fmaxf(fmaxf(attn[0], attn[1]), fmaxf(attn[2], attn[3]));
        float ee[4], ssum = 0.f;
#pragma unroll
        for (int l = 0; l < 4; l++) { ee[l] = __expf(attn[l] - mx); ssum += ee[l]; }
        const float inv = 1.f / ssum;
#pragma unroll
        for (int l = 0; l < 4; l++) {
            const float a = ee[l] * inv;
#pragma unroll
            for (int q = 0; q < 3; q++) sc[q] += a * ep[b * 4 + l][4 + q];
        }
#pragma unroll
        for (int q = 0; q < 3; q++)
#pragma unroll
            for (int off = 16; off; off >>= 1)
                sc[q] += __shfl_xor_sync(0xffffffffu, sc[q], off);
        if (lane == 0) { red[wp][0] = sc[0]; red[wp][1] = sc[1]; red[wp][2] = sc[2]; }
    }
    __syncthreads();
    if (tid < 3) {
        const float v = red[0][tid] + red[1][tid] + red[2][tid] + red[3][tid];
        g_tabctx[(t * 3 + s) * 3 + tid] = v;
    }
}

__global__ void serial_kernel()
{
    __shared__ float tab[255 * 9];
    __shared__ float xp[256 * 3];
    const int tid = threadIdx.x;
    for (int i = tid; i < 255 * 9; i += 256) tab[i] = g_tabctx[i];
    for (int i = tid; i < 256 * 3; i += 256) xp[i] = g_xproj[i];
    __syncthreads();
    if (tid == 0) {
        g_cur[0] = 0;
        int cur = 0;
        for (int tau = 1; tau < 256; tau++) {
            const float* tv = &tab[((tau - 1) * 3 + cur) * 3];
            const float v0 = tv[0] + xp[tau * 3 + 0];
            const float v1 = tv[1] + xp[tau * 3 + 1];
            const float v2 = tv[2] + xp[tau * 3 + 2];
            int c = 0; float best = v0;
            if (v1 > best) { best = v1; c = 1; }
            if (v2 > best) { best = v2; c = 2; }
            cur = c; g_cur[tau] = c;
        }
    }
}

__global__ __launch_bounds__(256)
void gather_kernel(float* __restrict__ out, long long n)
{
    const long long idx = (long long)blockIdx.x * 256 + threadIdx.x;
    if (idx >= n) return;
    const long long BTH = (long long)BB * TT * HH;
    int b, t, h;
    if (idx < BTH) {
        b = (int)(idx >> 16);
        const int r = (int)(idx & 65535);
        t = r >> 8; h = r & 255;
    } else {
        const long long j = idx - BTH;
        if (j >= (long long)BB * HH) { out[idx] = 0.f; return; }
        b = (int)(j >> 8); h = (int)(j & 255); t = TT - 1;
    }
    const int cur = g_cur[t];
    out[idx] = __half2float(
        g_hh[((size_t)(cur * LL + (LL - 1)) * MTOT + (size_t)b * TT + t) * HH + h]);
}

// ---------------------------------------------------------------------------
extern "C" void kernel_launch(void* const* d_in, const int* in_sizes, int n_in,
                              void* d_out, int out_size)
{
    (void)in_sizes; (void)n_in;
    const float* x      = (const float*)d_in[0];
    const float* hidden = (const float*)d_in[1];
    const float* w_ih0  = (const float*)d_in[2];
    const float* b_ih0  = (const float*)d_in[3];
    const float* b_hh0  = (const float*)d_in[4];
    const float* w_ih   = (const float*)d_in[5];
    const float* b_ih   = (const float*)d_in[6];
    const float* b_hh   = (const float*)d_in[7];
    const float* w_lw   = (const float*)d_in[8];
    const float* b_lw   = (const float*)d_in[9];
    const float* w_sel  = (const float*)d_in[10];
    const float* b_sel  = (const float*)d_in[11];
    float* out = (float*)d_out;

    __half *xh, *w0h, *wh, *hh;
    cudaGetSymbolAddress((void**)&xh,  g_xh);
    cudaGetSymbolAddress((void**)&w0h, g_w0h);
    cudaGetSymbolAddress((void**)&wh,  g_wh);
    cudaGetSymbolAddress((void**)&hh,  g_hh);

    f2h_kernel<<<(MTOT * II / 4 + 255) / 256, 256>>>(x, xh, MTOT * II / 4);
    f2h_kernel<<<(SS * 768 * 256 / 4 + 255) / 256, 256>>>(w_ih0, w0h, SS * 768 * 256 / 4);
    f2h_kernel<<<(SS * 3 * 768 * 256 / 4 + 255) / 256, 256>>>(w_ih, wh, SS * 3 * 768 * 256 / 4);

    cudaFuncSetAttribute(gru_mma_kernel,
                         cudaFuncAttributeMaxDynamicSharedMemorySize, SM_TOTAL);
    cudaFuncSetAttribute(proj_kernel,
                         cudaFuncAttributeMaxDynamicSharedMemorySize, SM_TOTAL);

    const size_t hstride = (size_t)LL * MTOT * HH;

    // layer 0 GEMM + fused xproj blocks (xproj depends only on x)
    gru_mma_kernel<<<NTILES + 255, 256, SM_TOTAL>>>(
        xh, 0, w0h, (long long)768 * 256,
        b_ih0, b_hh0, 768,
        hh + 0 * (size_t)MTOT * HH,
        w_lw, w_sel, x, b_sel, 1, 0);

    // layers 1..3 GEMM + fused proj blocks for layer l-1 (hh[l-1] complete)
    for (int l = 1; l < LL; l++) {
        gru_mma_kernel<<<NTILES + 768, 256, SM_TOTAL>>>(
            hh + (size_t)(l - 1) * MTOT * HH, (long long)hstride,
            wh + (size_t)(l - 1) * 768 * 256, (long long)3 * 768 * 256,
            b_ih + (size_t)(l - 1) * 768,
            b_hh + (size_t)(l - 1) * 768, 3 * 768,
            hh + (size_t)l * MTOT * HH,
            w_lw, w_sel, x, b_sel, 2, l - 1);
    }

    // final layer projection (standalone)
    proj_kernel<<<768, 256, SM_TOTAL>>>(w_lw, w_sel, LL - 1);

    table_kernel<<<dim3(255, 3), 256>>>(hidden, b_lw);
    serial_kernel<<<1, 256>>>();

    const long long n = (long long)out_size;
    const int nb = (int)((n + 255) / 256);
    gather_kernel<<<nb, 256>>>(out, n);
}

// round 16
// speedup vs baseline: 1.1067x; 1.0595x over previous
#include <cuda_runtime.h>
#include <cuda_fp16.h>
#include <cstdint>

// Problem constants
#define BB 128
#define TT 256
#define II 256
#define HH 256
#define LL 4
#define SS 3
#define KK 256
#define MTOT (BB*TT)
#define SLM ((size_t)SS * LL * MTOT)

// Scratch
__device__ __half g_hh[(size_t)SS * LL * MTOT * HH];  // fp16 h (GEMM A / proj / gather)
__device__ __half g_xh[(size_t)MTOT * II];            // fp16 x
__device__ __half g_w0h[(size_t)SS * 768 * 256];      // fp16 w_ih0
__device__ __half g_wh [(size_t)SS * 3 * 768 * 256];  // fp16 w_ih
__device__ float g_ep[SLM * 8];                       // projections [sl*M + m][8]
__device__ float g_tabctx[255 * 3 * 3];
__device__ float g_xproj[256 * 3];
__device__ int   g_cur[256];

__device__ __forceinline__ float sigf(float x) {
    return __fdividef(1.f, 1.f + __expf(-x));
}
__device__ __forceinline__ float gruf(float gr, float gz, float gn, float bh) {
    const float r = sigf(gr);
    const float z = sigf(gz);
    const float n = 2.f * sigf(2.f * (gn + r * bh)) - 1.f;
    return (1.f - z) * n;
}
__device__ __forceinline__ uint32_t smem_u32(const void* p) {
    uint32_t a;
    asm("{ .reg .u64 t; cvta.to.shared.u64 t, %1; cvt.u32.u64 %0, t; }" : "=r"(a) : "l"(p));
    return a;
}
__device__ __forceinline__ void mma_f16(float* c, const uint32_t* a, const uint32_t* b) {
    asm volatile(
        "mma.sync.aligned.m16n8k16.row.col.f32.f16.f16.f32 "
        "{%0,%1,%2,%3}, {%4,%5,%6,%7}, {%8,%9}, {%0,%1,%2,%3};"
        : "+f"(c[0]), "+f"(c[1]), "+f"(c[2]), "+f"(c[3])
        : "r"(a[0]), "r"(a[1]), "r"(a[2]), "r"(a[3]), "r"(b[0]), "r"(b[1]));
}
#define LDSM4(r0, r1, r2, r3, addr) \
    asm volatile("ldmatrix.sync.aligned.m8n8.x4.shared.b16 {%0,%1,%2,%3}, [%4];" \
        : "=r"(r0), "=r"(r1), "=r"(r2), "=r"(r3) : "r"(addr))
#define LDSM2(r0, r1, addr) \
    asm volatile("ldmatrix.sync.aligned.m8n8.x2.shared.b16 {%0,%1}, [%2];" \
        : "=r"(r0), "=r"(r1) : "r"(addr))
#define CP16(dst, src) \
    asm volatile("cp.async.cg.shared.global [%0], [%1], 16;" :: "r"(dst), "l"(src))
#define CP_COMMIT() asm volatile("cp.async.commit_group;" ::: "memory")
#define CP_WAITN(n) asm volatile("cp.async.wait_group %0;" :: "n"(n) : "memory")

// ---- main GEMM SMEM: 4 stages x (A[128][64]h + W[96][64]h); bias @ 114688 ----
#define STAGE_BYTES 28672
#define W_OFF       16384
#define SM_BIAS     114688
#define SM_TOTAL    115200

// ---------------------------------------------------------------------------
// fp16 mma.sync GEMM + register-resident GRU gating (R13 structure, verbatim).
// CTA: 128 M x 96 N. 8 warps (4m x 2n), warp tile 32x48, 2 CTAs/SM.
// Full-K prefetch: 4 commit groups, cascading wait_group 3/2/1/0.
// W rows gate-interleaved per 8-col tile (tile t -> gate t%3, h-octet t/3).
// ---------------------------------------------------------------------------
__global__ void __launch_bounds__(256, 2)
gru_mma_kernel(const __half* __restrict__ Ag, long long sAs,
               const __half* __restrict__ Wg, long long sWs,
               const float* __restrict__ BIg, const float* __restrict__ BHg, int sBs,
               __half* __restrict__ Ohg)
{
    extern __shared__ char smem[];
    const uint32_t sbase = smem_u32(smem);
    float* sbias = (float*)(smem + SM_BIAS);

    const int tid = threadIdx.x;
    const int wid = tid >> 5;
    const int lane = tid & 31;
    const int lq = lane >> 2;
    const int lr = lane & 3;

    const int s = blockIdx.z;
    const __half* A = Ag + (size_t)s * sAs;
    const __half* W = Wg + (size_t)s * sWs;
    const float* BI = BIg + s * sBs;
    const float* BH = BHg + s * sBs;
    __half* Oh = Ohg + (size_t)s * ((size_t)LL * MTOT * HH);

    const int hb = blockIdx.x * 32;
    const int mBase = blockIdx.y * 128;

    const int wm = (wid & 3) * 32;
    const int wn = (wid >> 2) * 48;
    const int warp_n = wid >> 2;

    const int arow = tid >> 3;
    const int seg  = tid & 7;
    auto load_stage = [&](int buf, int k0) {
        const uint32_t stA = sbase + buf * STAGE_BYTES;
#pragma unroll
        for (int j = 0; j < 4; ++j) {
            const int row = arow + 32 * j;
            const uint32_t dst = stA + row * 128 + ((seg ^ (row & 7)) * 16);
            CP16(dst, A + (size_t)(mBase + row) * KK + k0 + seg * 8);
        }
#pragma unroll
        for (int j = 0; j < 3; ++j) {
            const int n = arow + 32 * j;               // 0..95
            const int t = n >> 3, c = n & 7;
            const int grow = (t % 3) * 256 + hb + (t / 3) * 8 + c;  // gate-interleaved
            const uint32_t dst = stA + W_OFF + n * 128 + ((seg ^ (n & 7)) * 16);
            CP16(dst, W + (size_t)grow * KK + k0 + seg * 8);
        }
    };

    // prefetch entire K (4 chunks of 64), one commit group each
    load_stage(0, 0);   CP_COMMIT();
    load_stage(1, 64);  CP_COMMIT();
    load_stage(2, 128); CP_COMMIT();
    load_stage(3, 192); CP_COMMIT();

    if (tid < 32)       sbias[tid] = __ldg(&BI[hb + tid])            + __ldg(&BH[hb + tid]);
    else if (tid < 64)  sbias[tid] = __ldg(&BI[256 + hb + tid - 32]) + __ldg(&BH[256 + hb + tid - 32]);
    else if (tid < 96)  sbias[tid] = __ldg(&BI[512 + hb + tid - 64]);
    else if (tid < 128) sbias[tid] = __ldg(&BH[512 + hb + tid - 96]);

    float acc[2][6][4];
#pragma unroll
    for (int mt = 0; mt < 2; mt++)
#pragma unroll
        for (int nt = 0; nt < 6; nt++)
#pragma unroll
            for (int q = 0; q < 4; q++) acc[mt][nt][q] = 0.f;

    const int rA_lo = lane & 15;
    const int sA    = lane >> 4;
    const int rB_lo = ((lane >> 4) << 3) + (lane & 7);
    const int sB    = (lane >> 3) & 1;

    auto compute = [&](int buf) {
        const uint32_t stA = sbase + buf * STAGE_BYTES;
        const uint32_t stW = stA + W_OFF;
#pragma unroll
        for (int kk = 0; kk < 4; ++kk) {
            uint32_t a[2][4];
#pragma unroll
            for (int mt = 0; mt < 2; mt++) {
                const int row = wm + mt * 16 + rA_lo;
                const uint32_t addr = stA + row * 128
                                    + (((kk * 2 + sA) ^ (row & 7)) * 16);
                LDSM4(a[mt][0], a[mt][1], a[mt][2], a[mt][3], addr);
            }
            uint32_t b[6][2];
#pragma unroll
            for (int np = 0; np < 3; np++) {
                const int n = wn + np * 16 + rB_lo;
                const uint32_t addr = stW + n * 128
                                    + (((kk * 2 + sB) ^ (n & 7)) * 16);
                uint32_t r0, r1, r2, r3;
                LDSM4(r0, r1, r2, r3, addr);
                b[2 * np][0] = r0; b[2 * np][1] = r1;
                b[2 * np + 1][0] = r2; b[2 * np + 1][1] = r3;
            }
#pragma unroll
            for (int mt = 0; mt < 2; mt++)
#pragma unroll
                for (int nt = 0; nt < 6; nt++)
                    mma_f16(acc[mt][nt], a[mt], b[nt]);
        }
    };

    CP_WAITN(3); __syncthreads(); compute(0);
    CP_WAITN(2); __syncthreads(); compute(1);
    CP_WAITN(1); __syncthreads(); compute(2);
    CP_WAITN(0); __syncthreads(); compute(3);

    // -------- register-resident GRU epilogue (fp16 store only) --------
#pragma unroll
    for (int o = 0; o < 2; ++o) {
        const int hl = (warp_n * 2 + o) * 8 + 2 * lr;
        const float br0 = sbias[hl],       br1 = sbias[hl + 1];
        const float bz0 = sbias[32 + hl],  bz1 = sbias[33 + hl];
        const float bn0 = sbias[64 + hl],  bn1 = sbias[65 + hl];
        const float bh0 = sbias[96 + hl],  bh1 = sbias[97 + hl];
#pragma unroll
        for (int mt = 0; mt < 2; ++mt) {
#pragma unroll
            for (int hf = 0; hf < 2; ++hf) {
                const int row = mBase + wm + mt * 16 + lq + hf * 8;
                const int q = hf * 2;
                const float hv0 = gruf(acc[mt][o * 3 + 0][q]     + br0,
                                       acc[mt][o * 3 + 1][q]     + bz0,
                                       acc[mt][o * 3 + 2][q]     + bn0, bh0);
                const float hv1 = gruf(acc[mt][o * 3 + 0][q + 1] + br1,
                                       acc[mt][o * 3 + 1][q + 1] + bz1,
                                       acc[mt][o * 3 + 2][q + 1] + bn1, bh1);
                *(__half2*)&Oh[(size_t)row * HH + hb + hl] = __floats2half2_rn(hv0, hv1);
            }
        }
    }
}

// ---------------------------------------------------------------------------
// Skinny projection GEMM (per-layer): g_ep rows of plane (s, layer). (R13)
// ---------------------------------------------------------------------------
#define PJ_STAGE 16384
#define PJ_B_OFF 49152
#define PJ_TOTAL 53376
#define PJ_BSTRIDE 264

__global__ void __launch_bounds__(256)
proj_kernel(const float* __restrict__ w_lw, const float* __restrict__ w_sel,
            int layer)
{
    extern __shared__ char smem[];
    const uint32_t sbase = smem_u32(smem);
    __half* Bs = (__half*)(smem + PJ_B_OFF);

    const int tid = threadIdx.x;
    const int wid = tid >> 5;
    const int lane = tid & 31;
    const int lq = lane >> 2;
    const int lr = lane & 3;

    const int s = blockIdx.y;
    const size_t rowBase = ((size_t)(s * LL + layer) * MTOT) + (size_t)blockIdx.x * 128;
    const __half* A = g_hh + rowBase * 256;

    for (int i = tid; i < 8 * PJ_BSTRIDE; i += 256) {
        const int n = i / PJ_BSTRIDE, k = i % PJ_BSTRIDE;
        float v = 0.f;
        if (k < 256 && n < 7)
            v = (n < 4) ? __ldg(&w_lw[n * 256 + k]) : __ldg(&w_sel[(n - 4) * 512 + k]);
        Bs[i] = __float2half_rn(v);
    }

    const int arow = tid >> 3;
    const int seg  = tid & 7;
    auto load_stage = [&](int buf, int k0) {
        const uint32_t st = sbase + buf * PJ_STAGE;
#pragma unroll
        for (int j = 0; j < 4; ++j) {
            const int row = arow + 32 * j;
            const uint32_t dst = st + row * 128 + ((seg ^ (row & 7)) * 16);
            CP16(dst, A + (size_t)row * 256 + k0 + seg * 8);
        }
    };

    const int rA_lo = lane & 15;
    const int sA    = lane >> 4;
    const int l4    = lane & 15;
    const uint32_t bAddrBase = sbase + PJ_B_OFF
                             + (uint32_t)((l4 & 7) * PJ_BSTRIDE * 2 + ((l4 >> 3) & 1) * 16);

    float acc[4] = {0.f, 0.f, 0.f, 0.f};

    load_stage(0, 0);   CP_COMMIT();
    load_stage(1, 64);  CP_COMMIT();

#pragma unroll 1
    for (int st = 0; st < 4; ++st) {
        CP_WAITN(1);
        __syncthreads();
        const uint32_t stA = sbase + (st % 3) * PJ_STAGE;

#pragma unroll
        for (int kk = 0; kk < 4; ++kk) {
            uint32_t a[4];
            const int row = wid * 16 + rA_lo;
            const uint32_t addr = stA + row * 128
                                + (((kk * 2 + sA) ^ (row & 7)) * 16);
            LDSM4(a[0], a[1], a[2], a[3], addr);

            uint32_t b[2];
            const int k0 = st * 64 + kk * 16;
            LDSM2(b[0], b[1], bAddrBase + k0 * 2);

            mma_f16(acc, a, b);
        }

        if (st + 2 < 4) load_stage((st + 2) % 3, (st + 2) * 64);
        CP_COMMIT();
    }

    const size_t r0 = rowBase + wid * 16 + lq;
    *(float2*)(g_ep + r0 * 8 + 2 * lr)       = make_float2(acc[0], acc[1]);
    *(float2*)(g_ep + (r0 + 8) * 8 + 2 * lr) = make_float2(acc[2], acc[3]);
}

// ---------------------------------------------------------------------------
// Merged fp32 -> fp16 (rna) conversion for x, w_ih0, w_ih in one launch
// ---------------------------------------------------------------------------
#define N4_X  (MTOT * II / 4)                 // 2097152
#define N4_W0 (SS * 768 * 256 / 4)            // 147456
#define N4_W  (SS * 3 * 768 * 256 / 4)        // 442368
#define N4_ALL (N4_X + N4_W0 + N4_W)

__global__ __launch_bounds__(256)
void f2h_all_kernel(const float* __restrict__ x,
                    const float* __restrict__ w_ih0,
                    const float* __restrict__ w_ih)
{
    const int i = blockIdx.x * 256 + threadIdx.x;
    if (i >= N4_ALL) return;
    const float* src;
    __half* dst;
    int j;
    if (i < N4_X)                 { src = x;     dst = g_xh;  j = i; }
    else if (i < N4_X + N4_W0)    { src = w_ih0; dst = g_w0h; j = i - N4_X; }
    else                          { src = w_ih;  dst = g_wh;  j = i - N4_X - N4_W0; }
    const float4 v = __ldg((const float4*)src + j);
    __half2* d = (__half2*)dst + 2 * j;
    d[0] = __floats2half2_rn(v.x, v.y);
    d[1] = __floats2half2_rn(v.z, v.w);
}

// ---------------------------------------------------------------------------
// table (+xproj folded in as grid.y == 3 slice)
// ---------------------------------------------------------------------------
__global__ __launch_bounds__(256)
void table_kernel(const float* __restrict__ hidden,
                  const float* __restrict__ b_lw,
                  const float* __restrict__ x,
                  const float* __restrict__ w_sel,
                  const float* __restrict__ b_sel)
{
    const int tid = threadIdx.x;
    const int lane = tid & 31;
    const int wp = tid >> 5;

    if (blockIdx.y == 3) {
        // ---- xproj body: tau = blockIdx.x + 1 ----
        __shared__ float redx[3][8];
        const int tau = blockIdx.x + 1;
        float xs = 0.f;
        const float* xp = x + (size_t)tau * II + tid;
#pragma unroll 4
        for (int b = 0; b < 128; b++) xs += __ldg(&xp[(size_t)b * TT * II]);
        float sc[3];
#pragma unroll
        for (int q = 0; q < 3; q++) sc[q] = xs * __ldg(&w_sel[q * 512 + 256 + tid]);
#pragma unroll
        for (int q = 0; q < 3; q++)
#pragma unroll
            for (int off = 16; off; off >>= 1)
                sc[q] += __shfl_xor_sync(0xffffffffu, sc[q], off);
        if (lane == 0) { redx[0][wp] = sc[0]; redx[1][wp] = sc[1]; redx[2][wp] = sc[2]; }
        __syncthreads();
        if (tid < 3) {
            float v = 0.f;
#pragma unroll
            for (int w2 = 0; w2 < 8; w2++) v += redx[tid][w2];
            g_xproj[tau * 3 + tid] = v + 128.f * __ldg(&b_sel[tid]);
        }
        return;
    }

    const int t = blockIdx.x;
    const int s = blockIdx.y;

    __shared__ float ep[512][8];
    __shared__ float red[4][3];

    for (int i = tid; i < 1024; i += 256) {
        const int p = i >> 1;
        const int half = i & 1;
        const int b = p >> 2, l = p & 3;
        const size_t idx = (((size_t)(s * LL + l) * MTOT + (size_t)b * TT + t) * 8
                           + half * 4);
        ((float4*)ep)[i] = *(const float4*)(g_ep + idx);
    }
    __syncthreads();

    float sc[3] = {0.f, 0.f, 0.f};
    if (tid < 128) {
        const int b = tid;
        float bl[4];
#pragma unroll
        for (int lp = 0; lp < 4; lp++) bl[lp] = __ldg(&b_lw[lp]);
        float attn[4];
#pragma unroll
        for (int l = 0; l < 4; l++) {
            float a = 0.f;
#pragma unroll
            for (int lp = 0; lp < 4; lp++)
                a += __ldg(&hidden[b * 16 + l * 4 + lp]) * (ep[b * 4 + l][lp] + bl[lp]);
            attn[l] = a;
        }
        const float mx = fmaxf(fmaxf(attn[0], attn[1]), fmaxf(attn[2], attn[3]));
        float ee[4], ssum = 0.f;
#pragma unroll
        for (int l = 0; l < 4; l++) { ee[l] = __expf(attn[l] - mx); ssum += ee[l]; }
        const float inv = 1.f / ssum;
#pragma unroll
        for (int l = 0; l < 4; l++) {
            const float a = ee[l] * inv;
#pragma unroll
            for (int q = 0; q < 3; q++) sc[q] += a * ep[b * 4 + l][4 + q];
        }
#pragma unroll
        for (int q = 0; q < 3; q++)
#pragma unroll
            for (int off = 16; off; off >>= 1)
                sc[q] += __shfl_xor_sync(0xffffffffu, sc[q], off);
        if (lane == 0) { red[wp][0] = sc[0]; red[wp][1] = sc[1]; red[wp][2] = sc[2]; }
    }
    __syncthreads();
    if (tid < 3) {
        const float v = red[0][tid] + red[1][tid] + red[2][tid] + red[3][tid];
        g_tabctx[(t * 3 + s) * 3 + tid] = v;
    }
}

__global__ void serial_kernel()
{
    __shared__ float tab[255 * 9];
    __shared__ float xp[256 * 3];
    const int tid = threadIdx.x;
    for (int i = tid; i < 255 * 9; i += 256) tab[i] = g_tabctx[i];
    for (int i = tid; i < 256 * 3; i += 256) xp[i] = g_xproj[i];
    __syncthreads();
    if (tid == 0) {
        g_cur[0] = 0;
        int cur = 0;
        for (int tau = 1; tau < 256; tau++) {
            const float* tv = &tab[((tau - 1) * 3 + cur) * 3];
            const float v0 = tv[0] + xp[tau * 3 + 0];
            const float v1 = tv[1] + xp[tau * 3 + 1];
            const float v2 = tv[2] + xp[tau * 3 + 2];
            int c = 0; float best = v0;
            if (v1 > best) { best = v1; c = 1; }
            if (v2 > best) { best = v2; c = 2; }
            cur = c; g_cur[tau] = c;
        }
    }
}

__global__ __launch_bounds__(256)
void gather_kernel(float* __restrict__ out, long long n)
{
    const long long idx = (long long)blockIdx.x * 256 + threadIdx.x;
    if (idx >= n) return;
    const long long BTH = (long long)BB * TT * HH;
    int b, t, h;
    if (idx < BTH) {
        b = (int)(idx >> 16);
        const int r = (int)(idx & 65535);
        t = r >> 8; h = r & 255;
    } else {
        const long long j = idx - BTH;
        if (j >= (long long)BB * HH) { out[idx] = 0.f; return; }
        b = (int)(j >> 8); h = (int)(j & 255); t = TT - 1;
    }
    const int cur = g_cur[t];
    out[idx] = __half2float(
        g_hh[((size_t)(cur * LL + (LL - 1)) * MTOT + (size_t)b * TT + t) * HH + h]);
}

// ---------------------------------------------------------------------------
extern "C" void kernel_launch(void* const* d_in, const int* in_sizes, int n_in,
                              void* d_out, int out_size)
{
    (void)in_sizes; (void)n_in;
    const float* x      = (const float*)d_in[0];
    const float* hidden = (const float*)d_in[1];
    const float* w_ih0  = (const float*)d_in[2];
    const float* b_ih0  = (const float*)d_in[3];
    const float* b_hh0  = (const float*)d_in[4];
    const float* w_ih   = (const float*)d_in[5];
    const float* b_ih   = (const float*)d_in[6];
    const float* b_hh   = (const float*)d_in[7];
    const float* w_lw   = (const float*)d_in[8];
    const float* b_lw   = (const float*)d_in[9];
    const float* w_sel  = (const float*)d_in[10];
    const float* b_sel  = (const float*)d_in[11];
    float* out = (float*)d_out;

    __half *xh, *w0h, *wh, *hh;
    cudaGetSymbolAddress((void**)&xh,  g_xh);
    cudaGetSymbolAddress((void**)&w0h, g_w0h);
    cudaGetSymbolAddress((void**)&wh,  g_wh);
    cudaGetSymbolAddress((void**)&hh,  g_hh);

    f2h_all_kernel<<<(N4_ALL + 255) / 256, 256>>>(x, w_ih0, w_ih);

    cudaFuncSetAttribute(gru_mma_kernel,
                         cudaFuncAttributeMaxDynamicSharedMemorySize, SM_TOTAL);
    cudaFuncSetAttribute(proj_kernel,
                         cudaFuncAttributeMaxDynamicSharedMemorySize, PJ_TOTAL);

    const dim3 gGemm(HH / 32, MTOT / 128, SS);   // hb fastest: A-tile locality
    const dim3 gProj(MTOT / 128, SS);
    const size_t hstride = (size_t)LL * MTOT * HH;

    // layer 0, then L2-hot projection for layer 0
    gru_mma_kernel<<<gGemm, 256, SM_TOTAL>>>(
        xh, 0, w0h, (long long)768 * 256,
        b_ih0, b_hh0, 768,
        hh + 0 * (size_t)MTOT * HH);
    proj_kernel<<<gProj, 256, PJ_TOTAL>>>(w_lw, w_sel, 0);

    for (int l = 1; l < LL; l++) {
        gru_mma_kernel<<<gGemm, 256, SM_TOTAL>>>(
            hh + (size_t)(l - 1) * MTOT * HH, (long long)hstride,
            wh + (size_t)(l - 1) * 768 * 256, (long long)3 * 768 * 256,
            b_ih + (size_t)(l - 1) * 768,
            b_hh + (size_t)(l - 1) * 768, 3 * 768,
            hh + (size_t)l * MTOT * HH);
        proj_kernel<<<gProj, 256, PJ_TOTAL>>>(w_lw, w_sel, l);
    }

    table_kernel<<<dim3(255, 4), 256>>>(hidden, b_lw, x, w_sel, b_sel);
    serial_kernel<<<1, 256>>>();

    const long long n = (long long)out_size;
    const int nb = (int)((n + 255) / 256);
    gather_kernel<<<nb, 256>>>(out, n);
}

// round 17
// speedup vs baseline: 1.1460x; 1.0355x over previous
#include <cuda_runtime.h>
#include <cuda_fp16.h>
#include <cstdint>

// Problem constants
#define BB 128
#define TT 256
#define II 256
#define HH 256
#define LL 4
#define SS 3
#define KK 256
#define MTOT (BB*TT)
#define SLM ((size_t)SS * LL * MTOT)

// Scratch
__device__ __half g_hh[(size_t)SS * LL * MTOT * HH];  // fp16 h (GEMM A / proj / gather)
__device__ __half g_xh[(size_t)MTOT * II];            // fp16 x
__device__ __half g_w0h[(size_t)SS * 768 * 256];      // fp16 w_ih0
__device__ __half g_wh [(size_t)SS * 3 * 768 * 256];  // fp16 w_ih
__device__ float g_ep[SLM * 8];                       // projections [sl*M + m][8]
__device__ float g_tabctx[255 * 3 * 3];
__device__ float g_xproj[256 * 3];
__device__ int   g_cur[256];

__device__ __forceinline__ float sigf(float x) {
    return __fdividef(1.f, 1.f + __expf(-x));
}
__device__ __forceinline__ float gruf(float gr, float gz, float gn, float bh) {
    const float r = sigf(gr);
    const float z = sigf(gz);
    const float n = 2.f * sigf(2.f * (gn + r * bh)) - 1.f;
    return (1.f - z) * n;
}
__device__ __forceinline__ uint32_t smem_u32(const void* p) {
    uint32_t a;
    asm("{ .reg .u64 t; cvta.to.shared.u64 t, %1; cvt.u32.u64 %0, t; }" : "=r"(a) : "l"(p));
    return a;
}
__device__ __forceinline__ void mma_f16(float* c, const uint32_t* a, const uint32_t* b) {
    asm volatile(
        "mma.sync.aligned.m16n8k16.row.col.f32.f16.f16.f32 "
        "{%0,%1,%2,%3}, {%4,%5,%6,%7}, {%8,%9}, {%0,%1,%2,%3};"
        : "+f"(c[0]), "+f"(c[1]), "+f"(c[2]), "+f"(c[3])
        : "r"(a[0]), "r"(a[1]), "r"(a[2]), "r"(a[3]), "r"(b[0]), "r"(b[1]));
}
#define LDSM4(r0, r1, r2, r3, addr) \
    asm volatile("ldmatrix.sync.aligned.m8n8.x4.shared.b16 {%0,%1,%2,%3}, [%4];" \
        : "=r"(r0), "=r"(r1), "=r"(r2), "=r"(r3) : "r"(addr))
#define LDSM2(r0, r1, addr) \
    asm volatile("ldmatrix.sync.aligned.m8n8.x2.shared.b16 {%0,%1}, [%2];" \
        : "=r"(r0), "=r"(r1) : "r"(addr))
#define CP16(dst, src) \
    asm volatile("cp.async.cg.shared.global [%0], [%1], 16;" :: "r"(dst), "l"(src))
#define CP_COMMIT() asm volatile("cp.async.commit_group;" ::: "memory")
#define CP_WAITN(n) asm volatile("cp.async.wait_group %0;" :: "n"(n) : "memory")

// ---- main GEMM SMEM: 4 stages x (A[128][64]h + W[96][64]h); bias @ 114688 ----
#define STAGE_BYTES 28672
#define W_OFF       16384
#define SM_BIAS     114688
#define SM_TOTAL    115200

// ---------------------------------------------------------------------------
// fp16 mma.sync GEMM + register-resident GRU gating (R13/R16, verbatim).
// ---------------------------------------------------------------------------
__global__ void __launch_bounds__(256, 2)
gru_mma_kernel(const __half* __restrict__ Ag, long long sAs,
               const __half* __restrict__ Wg, long long sWs,
               const float* __restrict__ BIg, const float* __restrict__ BHg, int sBs,
               __half* __restrict__ Ohg)
{
    extern __shared__ char smem[];
    const uint32_t sbase = smem_u32(smem);
    float* sbias = (float*)(smem + SM_BIAS);

    const int tid = threadIdx.x;
    const int wid = tid >> 5;
    const int lane = tid & 31;
    const int lq = lane >> 2;
    const int lr = lane & 3;

    const int s = blockIdx.z;
    const __half* A = Ag + (size_t)s * sAs;
    const __half* W = Wg + (size_t)s * sWs;
    const float* BI = BIg + s * sBs;
    const float* BH = BHg + s * sBs;
    __half* Oh = Ohg + (size_t)s * ((size_t)LL * MTOT * HH);

    const int hb = blockIdx.x * 32;
    const int mBase = blockIdx.y * 128;

    const int wm = (wid & 3) * 32;
    const int wn = (wid >> 2) * 48;
    const int warp_n = wid >> 2;

    const int arow = tid >> 3;
    const int seg  = tid & 7;
    auto load_stage = [&](int buf, int k0) {
        const uint32_t stA = sbase + buf * STAGE_BYTES;
#pragma unroll
        for (int j = 0; j < 4; ++j) {
            const int row = arow + 32 * j;
            const uint32_t dst = stA + row * 128 + ((seg ^ (row & 7)) * 16);
            CP16(dst, A + (size_t)(mBase + row) * KK + k0 + seg * 8);
        }
#pragma unroll
        for (int j = 0; j < 3; ++j) {
            const int n = arow + 32 * j;               // 0..95
            const int t = n >> 3, c = n & 7;
            const int grow = (t % 3) * 256 + hb + (t / 3) * 8 + c;  // gate-interleaved
            const uint32_t dst = stA + W_OFF + n * 128 + ((seg ^ (n & 7)) * 16);
            CP16(dst, W + (size_t)grow * KK + k0 + seg * 8);
        }
    };

    load_stage(0, 0);   CP_COMMIT();
    load_stage(1, 64);  CP_COMMIT();
    load_stage(2, 128); CP_COMMIT();
    load_stage(3, 192); CP_COMMIT();

    if (tid < 32)       sbias[tid] = __ldg(&BI[hb + tid])            + __ldg(&BH[hb + tid]);
    else if (tid < 64)  sbias[tid] = __ldg(&BI[256 + hb + tid - 32]) + __ldg(&BH[256 + hb + tid - 32]);
    else if (tid < 96)  sbias[tid] = __ldg(&BI[512 + hb + tid - 64]);
    else if (tid < 128) sbias[tid] = __ldg(&BH[512 + hb + tid - 96]);

    float acc[2][6][4];
#pragma unroll
    for (int mt = 0; mt < 2; mt++)
#pragma unroll
        for (int nt = 0; nt < 6; nt++)
#pragma unroll
            for (int q = 0; q < 4; q++) acc[mt][nt][q] = 0.f;

    const int rA_lo = lane & 15;
    const int sA    = lane >> 4;
    const int rB_lo = ((lane >> 4) << 3) + (lane & 7);
    const int sB    = (lane >> 3) & 1;

    auto compute = [&](int buf) {
        const uint32_t stA = sbase + buf * STAGE_BYTES;
        const uint32_t stW = stA + W_OFF;
#pragma unroll
        for (int kk = 0; kk < 4; ++kk) {
            uint32_t a[2][4];
#pragma unroll
            for (int mt = 0; mt < 2; mt++) {
                const int row = wm + mt * 16 + rA_lo;
                const uint32_t addr = stA + row * 128
                                    + (((kk * 2 + sA) ^ (row & 7)) * 16);
                LDSM4(a[mt][0], a[mt][1], a[mt][2], a[mt][3], addr);
            }
            uint32_t b[6][2];
#pragma unroll
            for (int np = 0; np < 3; np++) {
                const int n = wn + np * 16 + rB_lo;
                const uint32_t addr = stW + n * 128
                                    + (((kk * 2 + sB) ^ (n & 7)) * 16);
                uint32_t r0, r1, r2, r3;
                LDSM4(r0, r1, r2, r3, addr);
                b[2 * np][0] = r0; b[2 * np][1] = r1;
                b[2 * np + 1][0] = r2; b[2 * np + 1][1] = r3;
            }
#pragma unroll
            for (int mt = 0; mt < 2; mt++)
#pragma unroll
                for (int nt = 0; nt < 6; nt++)
                    mma_f16(acc[mt][nt], a[mt], b[nt]);
        }
    };

    CP_WAITN(3); __syncthreads(); compute(0);
    CP_WAITN(2); __syncthreads(); compute(1);
    CP_WAITN(1); __syncthreads(); compute(2);
    CP_WAITN(0); __syncthreads(); compute(3);

#pragma unroll
    for (int o = 0; o < 2; ++o) {
        const int hl = (warp_n * 2 + o) * 8 + 2 * lr;
        const float br0 = sbias[hl],       br1 = sbias[hl + 1];
        const float bz0 = sbias[32 + hl],  bz1 = sbias[33 + hl];
        const float bn0 = sbias[64 + hl],  bn1 = sbias[65 + hl];
        const float bh0 = sbias[96 + hl],  bh1 = sbias[97 + hl];
#pragma unroll
        for (int mt = 0; mt < 2; ++mt) {
#pragma unroll
            for (int hf = 0; hf < 2; ++hf) {
                const int row = mBase + wm + mt * 16 + lq + hf * 8;
                const int q = hf * 2;
                const float hv0 = gruf(acc[mt][o * 3 + 0][q]     + br0,
                                       acc[mt][o * 3 + 1][q]     + bz0,
                                       acc[mt][o * 3 + 2][q]     + bn0, bh0);
                const float hv1 = gruf(acc[mt][o * 3 + 0][q + 1] + br1,
                                       acc[mt][o * 3 + 1][q + 1] + bz1,
                                       acc[mt][o * 3 + 2][q + 1] + bn1, bh1);
                *(__half2*)&Oh[(size_t)row * HH + hb + hl] = __floats2half2_rn(hv0, hv1);
            }
        }
    }
}

// ---------------------------------------------------------------------------
// Skinny projection GEMM (per-layer), R13 verbatim.
// ---------------------------------------------------------------------------
#define PJ_STAGE 16384
#define PJ_B_OFF 49152
#define PJ_TOTAL 53376
#define PJ_BSTRIDE 264

__global__ void __launch_bounds__(256)
proj_kernel(const float* __restrict__ w_lw, const float* __restrict__ w_sel,
            int layer)
{
    extern __shared__ char smem[];
    const uint32_t sbase = smem_u32(smem);
    __half* Bs = (__half*)(smem + PJ_B_OFF);

    const int tid = threadIdx.x;
    const int wid = tid >> 5;
    const int lane = tid & 31;
    const int lq = lane >> 2;
    const int lr = lane & 3;

    const int s = blockIdx.y;
    const size_t rowBase = ((size_t)(s * LL + layer) * MTOT) + (size_t)blockIdx.x * 128;
    const __half* A = g_hh + rowBase * 256;

    for (int i = tid; i < 8 * PJ_BSTRIDE; i += 256) {
        const int n = i / PJ_BSTRIDE, k = i % PJ_BSTRIDE;
        float v = 0.f;
        if (k < 256 && n < 7)
            v = (n < 4) ? __ldg(&w_lw[n * 256 + k]) : __ldg(&w_sel[(n - 4) * 512 + k]);
        Bs[i] = __float2half_rn(v);
    }

    const int arow = tid >> 3;
    const int seg  = tid & 7;
    auto load_stage = [&](int buf, int k0) {
        const uint32_t st = sbase + buf * PJ_STAGE;
#pragma unroll
        for (int j = 0; j < 4; ++j) {
            const int row = arow + 32 * j;
            const uint32_t dst = st + row * 128 + ((seg ^ (row & 7)) * 16);
            CP16(dst, A + (size_t)row * 256 + k0 + seg * 8);
        }
    };

    const int rA_lo = lane & 15;
    const int sA    = lane >> 4;
    const int l4    = lane & 15;
    const uint32_t bAddrBase = sbase + PJ_B_OFF
                             + (uint32_t)((l4 & 7) * PJ_BSTRIDE * 2 + ((l4 >> 3) & 1) * 16);

    float acc[4] = {0.f, 0.f, 0.f, 0.f};

    load_stage(0, 0);   CP_COMMIT();
    load_stage(1, 64);  CP_COMMIT();

#pragma unroll 1
    for (int st = 0; st < 4; ++st) {
        CP_WAITN(1);
        __syncthreads();
        const uint32_t stA = sbase + (st % 3) * PJ_STAGE;

#pragma unroll
        for (int kk = 0; kk < 4; ++kk) {
            uint32_t a[4];
            const int row = wid * 16 + rA_lo;
            const uint32_t addr = stA + row * 128
                                + (((kk * 2 + sA) ^ (row & 7)) * 16);
            LDSM4(a[0], a[1], a[2], a[3], addr);

            uint32_t b[2];
            const int k0 = st * 64 + kk * 16;
            LDSM2(b[0], b[1], bAddrBase + k0 * 2);

            mma_f16(acc, a, b);
        }

        if (st + 2 < 4) load_stage((st + 2) % 3, (st + 2) * 64);
        CP_COMMIT();
    }

    const size_t r0 = rowBase + wid * 16 + lq;
    *(float2*)(g_ep + r0 * 8 + 2 * lr)       = make_float2(acc[0], acc[1]);
    *(float2*)(g_ep + (r0 + 8) * 8 + 2 * lr) = make_float2(acc[2], acc[3]);
}

// ---------------------------------------------------------------------------
// Merged fp32 -> fp16 (rna) conversion (R16)
// ---------------------------------------------------------------------------
#define N4_X  (MTOT * II / 4)
#define N4_W0 (SS * 768 * 256 / 4)
#define N4_W  (SS * 3 * 768 * 256 / 4)
#define N4_ALL (N4_X + N4_W0 + N4_W)

__global__ __launch_bounds__(256)
void f2h_all_kernel(const float* __restrict__ x,
                    const float* __restrict__ w_ih0,
                    const float* __restrict__ w_ih)
{
    const int i = blockIdx.x * 256 + threadIdx.x;
    if (i >= N4_ALL) return;
    const float* src;
    __half* dst;
    int j;
    if (i < N4_X)                 { src = x;     dst = g_xh;  j = i; }
    else if (i < N4_X + N4_W0)    { src = w_ih0; dst = g_w0h; j = i - N4_X; }
    else                          { src = w_ih;  dst = g_wh;  j = i - N4_X - N4_W0; }
    const float4 v = __ldg((const float4*)src + j);
    __half2* d = (__half2*)dst + 2 * j;
    d[0] = __floats2half2_rn(v.x, v.y);
    d[1] = __floats2half2_rn(v.z, v.w);
}

// ---------------------------------------------------------------------------
// table (+xproj folded in as grid.y == 3 slice) — R16 verbatim
// ---------------------------------------------------------------------------
__global__ __launch_bounds__(256)
void table_kernel(const float* __restrict__ hidden,
                  const float* __restrict__ b_lw,
                  const float* __restrict__ x,
                  const float* __restrict__ w_sel,
                  const float* __restrict__ b_sel)
{
    const int tid = threadIdx.x;
    const int lane = tid & 31;
    const int wp = tid >> 5;

    if (blockIdx.y == 3) {
        __shared__ float redx[3][8];
        const int tau = blockIdx.x + 1;
        float xs = 0.f;
        const float* xp = x + (size_t)tau * II + tid;
#pragma unroll 4
        for (int b = 0; b < 128; b++) xs += __ldg(&xp[(size_t)b * TT * II]);
        float sc[3];
#pragma unroll
        for (int q = 0; q < 3; q++) sc[q] = xs * __ldg(&w_sel[q * 512 + 256 + tid]);
#pragma unroll
        for (int q = 0; q < 3; q++)
#pragma unroll
            for (int off = 16; off; off >>= 1)
                sc[q] += __shfl_xor_sync(0xffffffffu, sc[q], off);
        if (lane == 0) { redx[0][wp] = sc[0]; redx[1][wp] = sc[1]; redx[2][wp] = sc[2]; }
        __syncthreads();
        if (tid < 3) {
            float v = 0.f;
#pragma unroll
            for (int w2 = 0; w2 < 8; w2++) v += redx[tid][w2];
            g_xproj[tau * 3 + tid] = v + 128.f * __ldg(&b_sel[tid]);
        }
        return;
    }

    const int t = blockIdx.x;
    const int s = blockIdx.y;

    __shared__ float ep[512][8];
    __shared__ float red[4][3];

    for (int i = tid; i < 1024; i += 256) {
        const int p = i >> 1;
        const int half = i & 1;
        const int b = p >> 2, l = p & 3;
        const size_t idx = (((size_t)(s * LL + l) * MTOT + (size_t)b * TT + t) * 8
                           + half * 4);
        ((float4*)ep)[i] = *(const float4*)(g_ep + idx);
    }
    __syncthreads();

    float sc[3] = {0.f, 0.f, 0.f};
    if (tid < 128) {
        const int b = tid;
        float bl[4];
#pragma unroll
        for (int lp = 0; lp < 4; lp++) bl[lp] = __ldg(&b_lw[lp]);
        float attn[4];
#pragma unroll
        for (int l = 0; l < 4; l++) {
            float a = 0.f;
#pragma unroll
            for (int lp = 0; lp < 4; lp++)
                a += __ldg(&hidden[b * 16 + l * 4 + lp]) * (ep[b * 4 + l][lp] + bl[lp]);
            attn[l] = a;
        }
        const float mx = fmaxf(fmaxf(attn[0], attn[1]), fmaxf(attn[2], attn[3]));
        float ee[4], ssum = 0.f;
#pragma unroll
        for (int l = 0; l < 4; l++) { ee[l] = __expf(attn[l] - mx); ssum += ee[l]; }
        const float inv = 1.f / ssum;
#pragma unroll
        for (int l = 0; l < 4; l++) {
            const float a = ee[l] * inv;
#pragma unroll
            for (int q = 0; q < 3; q++) sc[q] += a * ep[b * 4 + l][4 + q];
        }
#pragma unroll
        for (int q = 0; q < 3; q++)
#pragma unroll
            for (int off = 16; off; off >>= 1)
                sc[q] += __shfl_xor_sync(0xffffffffu, sc[q], off);
        if (lane == 0) { red[wp][0] = sc[0]; red[wp][1] = sc[1]; red[wp][2] = sc[2]; }
    }
    __syncthreads();
    if (tid < 3) {
        const float v = red[0][tid] + red[1][tid] + red[2][tid] + red[3][tid];
        g_tabctx[(t * 3 + s) * 3 + tid] = v;
    }
}

// ---------------------------------------------------------------------------
// Parallel function-composition scan over the 255 transition maps.
// map_t(s) = argmax_{s'} (tab[t-1][s][s'] + xp[t][s']), first-max tie rule.
// comp[t] = m_t ∘ ... ∘ m_1 (inclusive scan); cur_t = comp[t](0).
// ---------------------------------------------------------------------------
__global__ void serial_kernel()
{
    __shared__ int comp[256];
    const int tid = threadIdx.x;

    int m = 0;
    if (tid >= 1) {
        const float xp0 = g_xproj[tid * 3 + 0];
        const float xp1 = g_xproj[tid * 3 + 1];
        const float xp2 = g_xproj[tid * 3 + 2];
#pragma unroll
        for (int s = 0; s < 3; ++s) {
            const float* tv = g_tabctx + ((tid - 1) * 3 + s) * 3;
            const float v0 = tv[0] + xp0;
            const float v1 = tv[1] + xp1;
            const float v2 = tv[2] + xp2;
            int c = 0; float best = v0;
            if (v1 > best) { best = v1; c = 1; }
            if (v2 > best) { c = 2; }
            m |= c << (2 * s);
        }
    }
    comp[tid] = m;
    __syncthreads();

#pragma unroll
    for (int off = 1; off < 256; off <<= 1) {
        int prev = 0, cur = 0;
        const bool act = (tid >= 1 + off);
        if (act) { prev = comp[tid - off]; cur = comp[tid]; }
        __syncthreads();
        if (act) {
            const int n0 = (cur >> (2 * ((prev >> 0) & 3))) & 3;
            const int n1 = (cur >> (2 * ((prev >> 2) & 3))) & 3;
            const int n2 = (cur >> (2 * ((prev >> 4) & 3))) & 3;
            comp[tid] = n0 | (n1 << 2) | (n2 << 4);
        }
        __syncthreads();
    }

    if (tid == 0) g_cur[0] = 0;
    else          g_cur[tid] = comp[tid] & 3;
}

// ---------------------------------------------------------------------------
// Vectorized gather: 2 outputs per thread (half2 -> float2)
// ---------------------------------------------------------------------------
__global__ __launch_bounds__(256)
void gather_kernel(float* __restrict__ out, long long n2)
{
    const long long i = (long long)blockIdx.x * 256 + threadIdx.x;
    if (i >= n2) return;
    const long long idx = 2 * i;
    const long long BTH = (long long)BB * TT * HH;
    int b, t, h;
    if (idx < BTH) {
        b = (int)(idx >> 16);
        const int r = (int)(idx & 65535);
        t = r >> 8; h = r & 255;
    } else {
        const long long j = idx - BTH;
        if (j >= (long long)BB * HH) { out[idx] = 0.f; out[idx + 1] = 0.f; return; }
        b = (int)(j >> 8); h = (int)(j & 255); t = TT - 1;
    }
    const int cur = g_cur[t];
    const __half2 v = *(const __half2*)&g_hh[
        ((size_t)(cur * LL + (LL - 1)) * MTOT + (size_t)b * TT + t) * HH + h];
    *(float2*)&out[idx] = make_float2(__low2float(v), __high2float(v));
}

// ---------------------------------------------------------------------------
extern "C" void kernel_launch(void* const* d_in, const int* in_sizes, int n_in,
                              void* d_out, int out_size)
{
    (void)in_sizes; (void)n_in;
    const float* x      = (const float*)d_in[0];
    const float* hidden = (const float*)d_in[1];
    const float* w_ih0  = (const float*)d_in[2];
    const float* b_ih0  = (const float*)d_in[3];
    const float* b_hh0  = (const float*)d_in[4];
    const float* w_ih   = (const float*)d_in[5];
    const float* b_ih   = (const float*)d_in[6];
    const float* b_hh   = (const float*)d_in[7];
    const float* w_lw   = (const float*)d_in[8];
    const float* b_lw   = (const float*)d_in[9];
    const float* w_sel  = (const float*)d_in[10];
    const float* b_sel  = (const float*)d_in[11];
    float* out = (float*)d_out;

    __half *xh, *w0h, *wh, *hh;
    cudaGetSymbolAddress((void**)&xh,  g_xh);
    cudaGetSymbolAddress((void**)&w0h, g_w0h);
    cudaGetSymbolAddress((void**)&wh,  g_wh);
    cudaGetSymbolAddress((void**)&hh,  g_hh);

    f2h_all_kernel<<<(N4_ALL + 255) / 256, 256>>>(x, w_ih0, w_ih);

    cudaFuncSetAttribute(gru_mma_kernel,
                         cudaFuncAttributeMaxDynamicSharedMemorySize, SM_TOTAL);
    cudaFuncSetAttribute(proj_kernel,
                         cudaFuncAttributeMaxDynamicSharedMemorySize, PJ_TOTAL);

    const dim3 gGemm(HH / 32, MTOT / 128, SS);   // hb fastest: A-tile locality
    const dim3 gProj(MTOT / 128, SS);
    const size_t hstride = (size_t)LL * MTOT * HH;

    gru_mma_kernel<<<gGemm, 256, SM_TOTAL>>>(
        xh, 0, w0h, (long long)768 * 256,
        b_ih0, b_hh0, 768,
        hh + 0 * (size_t)MTOT * HH);
    proj_kernel<<<gProj, 256, PJ_TOTAL>>>(w_lw, w_sel, 0);

    for (int l = 1; l < LL; l++) {
        gru_mma_kernel<<<gGemm, 256, SM_TOTAL>>>(
            hh + (size_t)(l - 1) * MTOT * HH, (long long)hstride,
            wh + (size_t)(l - 1) * 768 * 256, (long long)3 * 768 * 256,
            b_ih + (size_t)(l - 1) * 768,
            b_hh + (size_t)(l - 1) * 768, 3 * 768,
            hh + (size_t)l * MTOT * HH);
        proj_kernel<<<gProj, 256, PJ_TOTAL>>>(w_lw, w_sel, l);
    }

    table_kernel<<<dim3(255, 4), 256>>>(hidden, b_lw, x, w_sel, b_sel);
    serial_kernel<<<1, 256>>>();

    const long long n2 = (long long)out_size / 2;
    const int nb = (int)((n2 + 255) / 256);
    gather_kernel<<<nb, 256>>>(out, n2);
}